// round 3
// baseline (speedup 1.0000x reference)
#include <cuda_runtime.h>

#define NMAX   100000
#define EMAX   1600000
#define NGRAPH 64
#define NFEAT  128
#define NHID   64
#define NCLASS 10

// ---- scratch (allocation-free rule: __device__ globals) ----
__device__ int   g_src[EMAX];
__device__ int   g_dst[EMAX];
__device__ int   g_deg[NMAX];
__device__ float g_dinv[NMAX];
__device__ float g_hs  [(size_t)NMAX * NHID];
__device__ float g_accA[(size_t)NMAX * NHID];
__device__ float g_accB[(size_t)NMAX * NHID];
__device__ float g_gsum[NGRAPH * NHID];
__device__ int   g_gcnt[NGRAPH];

// ---------------------------------------------------------------------------
__global__ void k_init(int N) {
    int i = blockIdx.x * blockDim.x + threadIdx.x;
    if (i < N) g_deg[i] = 1;                 // self-loop contributes 1 to degree
    if (i < NGRAPH * NHID) g_gsum[i] = 0.f;
    if (i < NGRAPH) g_gcnt[i] = 0;
}

// edge index is int32 (JAX x64 disabled downcasts int64->int32).
// Bound-check defensively: invalid edges are dropped (rel_err signal, not crash).
__global__ void k_edge_prep(const int* __restrict__ ei, int E, int N) {
    int e = blockIdx.x * blockDim.x + threadIdx.x;
    if (e >= E) return;
    int s = ei[e];
    int d = ei[E + e];
    if ((unsigned)s >= (unsigned)N || (unsigned)d >= (unsigned)N) {
        g_src[e] = -1; g_dst[e] = -1; return;
    }
    g_src[e] = s;
    g_dst[e] = d;
    atomicAdd(&g_deg[d], 1);
}

__global__ void k_dinv(int N) {
    int i = blockIdx.x * blockDim.x + threadIdx.x;
    if (i < N) g_dinv[i] = rsqrtf((float)g_deg[i]);
}

// ---------------------------------------------------------------------------
// Layer 1 GEMM: hs[n] = dinv[n] * (x[n] @ W1);  accOut = hs (self-loop init)
// blockDim = 128 (64 cols x 2 halves), 8 nodes / block, 4 nodes / thread.
__global__ void k_gemm1(const float* __restrict__ x, const float* __restrict__ W,
                        float* __restrict__ accOut, int N) {
    __shared__ float Wsh[NFEAT * NHID];   // 32 KB
    __shared__ float xsh[8 * NFEAT];      // 4 KB
    int tid = threadIdx.x;
    for (int i = tid; i < NFEAT * NHID; i += 128) Wsh[i] = W[i];
    int nb = blockIdx.x * 8;
    for (int i = tid; i < 8 * NFEAT; i += 128) {
        int n = nb + (i >> 7);
        xsh[i] = (n < N) ? x[(size_t)n * NFEAT + (i & 127)] : 0.f;
    }
    __syncthreads();
    int c = tid & 63, half = tid >> 6;
    const float* xr = xsh + half * 4 * NFEAT;
    float a0 = 0.f, a1 = 0.f, a2 = 0.f, a3 = 0.f;
#pragma unroll 16
    for (int k = 0; k < NFEAT; k++) {
        float w = Wsh[k * NHID + c];
        a0 = fmaf(xr[k], w, a0);
        a1 = fmaf(xr[NFEAT + k], w, a1);
        a2 = fmaf(xr[2 * NFEAT + k], w, a2);
        a3 = fmaf(xr[3 * NFEAT + k], w, a3);
    }
    float acc[4] = {a0, a1, a2, a3};
    int n0 = nb + half * 4;
#pragma unroll
    for (int j = 0; j < 4; j++) {
        int n = n0 + j;
        if (n < N) {
            float v = g_dinv[n] * acc[j];
            g_hs [(size_t)n * NHID + c] = v;
            accOut[(size_t)n * NHID + c] = v;
        }
    }
}

// Layers 2/3 GEMM: input = relu(dinv[n]*accPrev[n] + bPrev) (fused finalize of
// previous layer), output hs = dinv[n]*(input @ W), accOut = hs.
__global__ void k_gemm23(const float* __restrict__ accPrev, const float* __restrict__ bPrev,
                         const float* __restrict__ W, float* __restrict__ accOut, int N) {
    __shared__ float Wsh[NHID * NHID];    // 16 KB
    __shared__ float xsh[8 * NHID];       // 2 KB
    int tid = threadIdx.x;
    for (int i = tid; i < NHID * NHID; i += 128) Wsh[i] = W[i];
    int nb = blockIdx.x * 8;
    for (int i = tid; i < 8 * NHID; i += 128) {
        int n = nb + (i >> 6);
        int k = i & 63;
        xsh[i] = (n < N)
            ? fmaxf(fmaf(g_dinv[n], accPrev[(size_t)n * NHID + k], bPrev[k]), 0.f)
            : 0.f;
    }
    __syncthreads();
    int c = tid & 63, half = tid >> 6;
    const float* xr = xsh + half * 4 * NHID;
    float a0 = 0.f, a1 = 0.f, a2 = 0.f, a3 = 0.f;
#pragma unroll 16
    for (int k = 0; k < NHID; k++) {
        float w = Wsh[k * NHID + c];
        a0 = fmaf(xr[k], w, a0);
        a1 = fmaf(xr[NHID + k], w, a1);
        a2 = fmaf(xr[2 * NHID + k], w, a2);
        a3 = fmaf(xr[3 * NHID + k], w, a3);
    }
    float acc[4] = {a0, a1, a2, a3};
    int n0 = nb + half * 4;
#pragma unroll
    for (int j = 0; j < 4; j++) {
        int n = n0 + j;
        if (n < N) {
            float v = g_dinv[n] * acc[j];
            g_hs [(size_t)n * NHID + c] = v;
            accOut[(size_t)n * NHID + c] = v;
        }
    }
}

// ---------------------------------------------------------------------------
// Edge scatter: acc[dst] += hs[src].  16 threads per edge, float4 gather +
// vectorized L2 reduction (red.global.add.v4.f32, sm_90+).
__global__ void k_edge(float* __restrict__ acc, int E) {
    long long idx = (long long)blockIdx.x * blockDim.x + threadIdx.x;
    if (idx >= (long long)E * 16) return;
    int e    = (int)(idx >> 4);
    int part = ((int)idx) & 15;
    int s = g_src[e];
    int d = g_dst[e];
    if (s < 0) return;   // dropped invalid edge
    const float4 v = *reinterpret_cast<const float4*>(&g_hs[(size_t)s * NHID + part * 4]);
    float* p = acc + (size_t)d * NHID + part * 4;
    asm volatile("red.global.add.v4.f32 [%0], {%1,%2,%3,%4};"
                 :: "l"(p), "f"(v.x), "f"(v.y), "f"(v.z), "f"(v.w) : "memory");
}

// ---------------------------------------------------------------------------
// Pool: per-graph sum of relu(dinv*acc3 + b3), plus node counts.
__global__ void k_pool(const float* __restrict__ acc3, const float* __restrict__ b3,
                       const int* __restrict__ batch, int N) {
    int idx = blockIdx.x * blockDim.x + threadIdx.x;
    if (idx >= N * NHID) return;
    int n = idx >> 6, c = idx & 63;
    float v = fmaxf(fmaf(g_dinv[n], acc3[idx], b3[c]), 0.f);
    int g = batch[n];
    if ((unsigned)g >= NGRAPH) return;
    atomicAdd(&g_gsum[g * NHID + c], v);
    if (c == 0) atomicAdd(&g_gcnt[g], 1);
}

// Head: logits = (gsum/cnt) @ Wl + bl, softmax. One thread per graph.
__global__ void k_head(const float* __restrict__ Wl, const float* __restrict__ bl,
                       float* __restrict__ out) {
    int g = threadIdx.x;
    if (g >= NGRAPH) return;
    float cnt = fmaxf((float)g_gcnt[g], 1.f);
    float inv = 1.f / cnt;
    float l[NCLASS];
#pragma unroll
    for (int c = 0; c < NCLASS; c++) l[c] = bl[c];
    for (int k = 0; k < NHID; k++) {
        float p = g_gsum[g * NHID + k] * inv;
#pragma unroll
        for (int c = 0; c < NCLASS; c++) l[c] = fmaf(p, Wl[k * NCLASS + c], l[c]);
    }
    float m = l[0];
#pragma unroll
    for (int c = 1; c < NCLASS; c++) m = fmaxf(m, l[c]);
    float s = 0.f;
#pragma unroll
    for (int c = 0; c < NCLASS; c++) { l[c] = __expf(l[c] - m); s += l[c]; }
    float is = 1.f / s;
#pragma unroll
    for (int c = 0; c < NCLASS; c++) out[g * NCLASS + c] = l[c] * is;
}

// ---------------------------------------------------------------------------
extern "C" void kernel_launch(void* const* d_in, const int* in_sizes, int n_in,
                              void* d_out, int out_size) {
    const float* x     = (const float*)d_in[0];
    const int*   ei    = (const int*)d_in[1];     // int32 (JAX x64 off)
    const int*   batch = (const int*)d_in[2];     // int32
    const float* W1 = (const float*)d_in[3];
    const float* b1 = (const float*)d_in[4];
    const float* W2 = (const float*)d_in[5];
    const float* b2 = (const float*)d_in[6];
    const float* W3 = (const float*)d_in[7];
    const float* b3 = (const float*)d_in[8];
    const float* Wl = (const float*)d_in[9];
    const float* bl = (const float*)d_in[10];
    float* out = (float*)d_out;

    int N = in_sizes[0] / NFEAT;
    int E = in_sizes[1] / 2;

    float *accA = nullptr, *accB = nullptr;
    cudaGetSymbolAddress((void**)&accA, g_accA);
    cudaGetSymbolAddress((void**)&accB, g_accB);

    const int T = 256;
    k_init<<<(N + T - 1) / T, T>>>(N);
    k_edge_prep<<<(E + T - 1) / T, T>>>(ei, E, N);
    k_dinv<<<(N + T - 1) / T, T>>>(N);

    int gemmBlocks = (N + 7) / 8;
    long long ework = (long long)E * 16;
    int eBlocks = (int)((ework + T - 1) / T);

    // Layer 1
    k_gemm1<<<gemmBlocks, 128>>>(x, W1, accA, N);
    k_edge<<<eBlocks, T>>>(accA, E);
    // Layer 2 (finalize of layer 1 fused into GEMM input load)
    k_gemm23<<<gemmBlocks, 128>>>(accA, b1, W2, accB, N);
    k_edge<<<eBlocks, T>>>(accB, E);
    // Layer 3
    k_gemm23<<<gemmBlocks, 128>>>(accB, b2, W3, accA, N);
    k_edge<<<eBlocks, T>>>(accA, E);

    // Pool + head
    k_pool<<<((N * NHID) + T - 1) / T, T>>>(accA, b3, batch, N);
    k_head<<<1, 64>>>(Wl, bl, out);
}

// round 4
// speedup vs baseline: 1.8507x; 1.8507x over previous
#include <cuda_runtime.h>

#define NMAX   100000
#define EMAX   1600000
#define NGRAPH 64
#define NFEAT  128
#define NHID   64
#define NCLASS 10
#define SCAN_B 512
#define NBLK_SCAN ((NMAX + SCAN_B - 1) / SCAN_B)   // 196

// ---- scratch (allocation-free rule: __device__ globals) ----
__device__ int   g_src[EMAX];
__device__ int   g_dst[EMAX];
__device__ int   g_csrc[EMAX];          // CSR: src ids grouped by dst
__device__ int   g_ecnt[NMAX];          // in-degree (edges only)
__device__ int   g_off[NMAX];           // CSR row offsets (exclusive scan)
__device__ int   g_cursor[NMAX];
__device__ int   g_scan[NMAX];
__device__ int   g_bsum[256];
__device__ int   g_boff[256];
__device__ float g_dinv[NMAX];
__device__ alignas(16) float g_hs  [(size_t)NMAX * NHID];
__device__ alignas(16) float g_accA[(size_t)NMAX * NHID];
__device__ alignas(16) float g_accB[(size_t)NMAX * NHID];
__device__ float g_gsum[NGRAPH * NHID];
__device__ int   g_gcnt[NGRAPH];

// ---------------------------------------------------------------------------
__global__ void k_init(int N) {
    int i = blockIdx.x * blockDim.x + threadIdx.x;
    if (i < N) g_ecnt[i] = 0;
    if (i < NGRAPH * NHID) g_gsum[i] = 0.f;
    if (i < NGRAPH) g_gcnt[i] = 0;
}

__global__ void k_edge_prep(const int* __restrict__ ei, int E, int N) {
    int e = blockIdx.x * blockDim.x + threadIdx.x;
    if (e >= E) return;
    int s = ei[e];
    int d = ei[E + e];
    if ((unsigned)s >= (unsigned)N || (unsigned)d >= (unsigned)N) {
        g_src[e] = -1; g_dst[e] = -1; return;
    }
    g_src[e] = s;
    g_dst[e] = d;
    atomicAdd(&g_ecnt[d], 1);
}

// ---- 3-kernel exclusive scan of g_ecnt -> g_off -------------------------
__device__ __forceinline__ int block_incl_scan(int v, int tid) {
    __shared__ int wsum[16];
    int lane = tid & 31, w = tid >> 5;
    int x = v;
#pragma unroll
    for (int o = 1; o < 32; o <<= 1) {
        int t = __shfl_up_sync(0xffffffffu, x, o);
        if (lane >= o) x += t;
    }
    if (lane == 31) wsum[w] = x;
    __syncthreads();
    if (w == 0) {
        int y = (lane < (blockDim.x >> 5)) ? wsum[lane] : 0;
#pragma unroll
        for (int o = 1; o < 16; o <<= 1) {
            int t = __shfl_up_sync(0xffffffffu, y, o);
            if (lane >= o) y += t;
        }
        if (lane < 16) wsum[lane] = y;
    }
    __syncthreads();
    return x + (w > 0 ? wsum[w - 1] : 0);
}

__global__ void k_scanA(int N) {
    int i = blockIdx.x * SCAN_B + threadIdx.x;
    int v = (i < N) ? g_ecnt[i] : 0;
    int incl = block_incl_scan(v, threadIdx.x);
    if (i < N) g_scan[i] = incl - v;
    if (threadIdx.x == SCAN_B - 1) g_bsum[blockIdx.x] = incl;
}

__global__ void k_scanB(int nb) {
    int t = threadIdx.x;
    int v = (t < nb) ? g_bsum[t] : 0;
    int incl = block_incl_scan(v, t);
    if (t < 256) g_boff[t] = incl - v;
}

__global__ void k_scanC(int N) {
    int i = blockIdx.x * SCAN_B + threadIdx.x;
    if (i >= N) return;
    int off = g_scan[i] + g_boff[blockIdx.x];
    g_off[i] = off;
    g_cursor[i] = off;
    g_dinv[i] = rsqrtf((float)(g_ecnt[i] + 1));   // +1 self-loop
}

__global__ void k_csr_fill(int E) {
    int e = blockIdx.x * blockDim.x + threadIdx.x;
    if (e >= E) return;
    int s = g_src[e];
    if (s < 0) return;
    int d = g_dst[e];
    int pos = atomicAdd(&g_cursor[d], 1);
    g_csrc[pos] = s;
}

// ---------------------------------------------------------------------------
// Layer 1 GEMM: hs[n] = dinv[n] * (x[n] @ W1).
// 128 threads, 32 nodes/block; each thread: 4 nodes x 4 cols, k blocked by 4.
__global__ void k_gemm1(const float* __restrict__ x, const float* __restrict__ W, int N) {
    __shared__ float4 Wsh[NFEAT * 16];   // [k][c4]  32KB
    __shared__ float4 xsh[32 * 32];      // [node][k4] 16KB
    int tid = threadIdx.x;
    const float4* W4 = reinterpret_cast<const float4*>(W);
    const float4* x4 = reinterpret_cast<const float4*>(x);
#pragma unroll
    for (int i = tid; i < NFEAT * 16; i += 128) Wsh[i] = W4[i];
    int nb = blockIdx.x * 32;
#pragma unroll
    for (int i = tid; i < 32 * 32; i += 128) {
        int n = nb + (i >> 5);
        xsh[i] = (n < N) ? x4[(size_t)n * 32 + (i & 31)]
                         : make_float4(0.f, 0.f, 0.f, 0.f);
    }
    __syncthreads();

    int cg = tid & 15;        // col group: cols cg*4..cg*4+3
    int ng = tid >> 4;        // node group: nodes ng*4..ng*4+3
    float4 a[4];
#pragma unroll
    for (int j = 0; j < 4; j++) a[j] = make_float4(0.f, 0.f, 0.f, 0.f);

#pragma unroll 4
    for (int k4 = 0; k4 < 32; k4++) {
        float4 w0 = Wsh[(4 * k4 + 0) * 16 + cg];
        float4 w1 = Wsh[(4 * k4 + 1) * 16 + cg];
        float4 w2 = Wsh[(4 * k4 + 2) * 16 + cg];
        float4 w3 = Wsh[(4 * k4 + 3) * 16 + cg];
#pragma unroll
        for (int j = 0; j < 4; j++) {
            float4 xv = xsh[(ng * 4 + j) * 32 + k4];
            a[j].x = fmaf(xv.x, w0.x, a[j].x); a[j].y = fmaf(xv.x, w0.y, a[j].y);
            a[j].z = fmaf(xv.x, w0.z, a[j].z); a[j].w = fmaf(xv.x, w0.w, a[j].w);
            a[j].x = fmaf(xv.y, w1.x, a[j].x); a[j].y = fmaf(xv.y, w1.y, a[j].y);
            a[j].z = fmaf(xv.y, w1.z, a[j].z); a[j].w = fmaf(xv.y, w1.w, a[j].w);
            a[j].x = fmaf(xv.z, w2.x, a[j].x); a[j].y = fmaf(xv.z, w2.y, a[j].y);
            a[j].z = fmaf(xv.z, w2.z, a[j].z); a[j].w = fmaf(xv.z, w2.w, a[j].w);
            a[j].x = fmaf(xv.w, w3.x, a[j].x); a[j].y = fmaf(xv.w, w3.y, a[j].y);
            a[j].z = fmaf(xv.w, w3.z, a[j].z); a[j].w = fmaf(xv.w, w3.w, a[j].w);
        }
    }
    float4* hs4 = reinterpret_cast<float4*>(g_hs);
#pragma unroll
    for (int j = 0; j < 4; j++) {
        int n = nb + ng * 4 + j;
        if (n < N) {
            float v = g_dinv[n];
            float4 o = a[j];
            o.x *= v; o.y *= v; o.z *= v; o.w *= v;
            hs4[(size_t)n * 16 + cg] = o;
        }
    }
}

// Layers 2/3 GEMM: in = relu(dinv*accPrev + bPrev); hs = dinv * (in @ W).
__global__ void k_gemm23(const float* __restrict__ accPrev, const float* __restrict__ bPrev,
                         const float* __restrict__ W, int N) {
    __shared__ float4 Wsh[NHID * 16];    // 16KB
    __shared__ float4 xsh[32 * 16];      // 8KB
    int tid = threadIdx.x;
    const float4* W4 = reinterpret_cast<const float4*>(W);
    const float4* acc4 = reinterpret_cast<const float4*>(accPrev);
    const float4* b4p = reinterpret_cast<const float4*>(bPrev);
#pragma unroll
    for (int i = tid; i < NHID * 16; i += 128) Wsh[i] = W4[i];
    int nb = blockIdx.x * 32;
#pragma unroll
    for (int i = tid; i < 32 * 16; i += 128) {
        int n = nb + (i >> 4);
        int k4 = i & 15;
        float4 o = make_float4(0.f, 0.f, 0.f, 0.f);
        if (n < N) {
            float4 av = acc4[(size_t)n * 16 + k4];
            float4 bb = b4p[k4];
            float dv = g_dinv[n];
            o.x = fmaxf(fmaf(dv, av.x, bb.x), 0.f);
            o.y = fmaxf(fmaf(dv, av.y, bb.y), 0.f);
            o.z = fmaxf(fmaf(dv, av.z, bb.z), 0.f);
            o.w = fmaxf(fmaf(dv, av.w, bb.w), 0.f);
        }
        xsh[i] = o;
    }
    __syncthreads();

    int cg = tid & 15;
    int ng = tid >> 4;
    float4 a[4];
#pragma unroll
    for (int j = 0; j < 4; j++) a[j] = make_float4(0.f, 0.f, 0.f, 0.f);

#pragma unroll 4
    for (int k4 = 0; k4 < 16; k4++) {
        float4 w0 = Wsh[(4 * k4 + 0) * 16 + cg];
        float4 w1 = Wsh[(4 * k4 + 1) * 16 + cg];
        float4 w2 = Wsh[(4 * k4 + 2) * 16 + cg];
        float4 w3 = Wsh[(4 * k4 + 3) * 16 + cg];
#pragma unroll
        for (int j = 0; j < 4; j++) {
            float4 xv = xsh[(ng * 4 + j) * 16 + k4];
            a[j].x = fmaf(xv.x, w0.x, a[j].x); a[j].y = fmaf(xv.x, w0.y, a[j].y);
            a[j].z = fmaf(xv.x, w0.z, a[j].z); a[j].w = fmaf(xv.x, w0.w, a[j].w);
            a[j].x = fmaf(xv.y, w1.x, a[j].x); a[j].y = fmaf(xv.y, w1.y, a[j].y);
            a[j].z = fmaf(xv.y, w1.z, a[j].z); a[j].w = fmaf(xv.y, w1.w, a[j].w);
            a[j].x = fmaf(xv.z, w2.x, a[j].x); a[j].y = fmaf(xv.z, w2.y, a[j].y);
            a[j].z = fmaf(xv.z, w2.z, a[j].z); a[j].w = fmaf(xv.z, w2.w, a[j].w);
            a[j].x = fmaf(xv.w, w3.x, a[j].x); a[j].y = fmaf(xv.w, w3.y, a[j].y);
            a[j].z = fmaf(xv.w, w3.z, a[j].z); a[j].w = fmaf(xv.w, w3.w, a[j].w);
        }
    }
    float4* hs4 = reinterpret_cast<float4*>(g_hs);
#pragma unroll
    for (int j = 0; j < 4; j++) {
        int n = nb + ng * 4 + j;
        if (n < N) {
            float v = g_dinv[n];
            float4 o = a[j];
            o.x *= v; o.y *= v; o.z *= v; o.w *= v;
            hs4[(size_t)n * 16 + cg] = o;
        }
    }
}

// ---------------------------------------------------------------------------
// CSR gather aggregation: acc[n] = hs[n] (self-loop) + sum_{s in in(n)} hs[s].
// One warp per node; 4 edges in flight (q=lane>>3), 8 lanes x 8 floats cover row.
__global__ void k_agg(float* __restrict__ accOut, int N) {
    int warp = (blockIdx.x * blockDim.x + threadIdx.x) >> 5;
    if (warp >= N) return;
    int lane = threadIdx.x & 31;
    int p = lane & 7;        // col chunk: float4s p*2, p*2+1
    int q = lane >> 3;       // edge slot 0..3
    const float4* hs4 = reinterpret_cast<const float4*>(g_hs);
    int n = warp;
    int start = g_off[n];
    int len = g_ecnt[n];

    float4 a0, a1;
    if (q == 0) {            // self-loop init
        a0 = hs4[(size_t)n * 16 + p * 2];
        a1 = hs4[(size_t)n * 16 + p * 2 + 1];
    } else {
        a0 = make_float4(0.f, 0.f, 0.f, 0.f);
        a1 = make_float4(0.f, 0.f, 0.f, 0.f);
    }
    for (int j = start + q; j < start + len; j += 4) {
        int s = g_csrc[j];
        float4 v0 = hs4[(size_t)s * 16 + p * 2];
        float4 v1 = hs4[(size_t)s * 16 + p * 2 + 1];
        a0.x += v0.x; a0.y += v0.y; a0.z += v0.z; a0.w += v0.w;
        a1.x += v1.x; a1.y += v1.y; a1.z += v1.z; a1.w += v1.w;
    }
    const unsigned F = 0xffffffffu;
#pragma unroll
    for (int off = 8; off <= 16; off <<= 1) {
        a0.x += __shfl_xor_sync(F, a0.x, off);
        a0.y += __shfl_xor_sync(F, a0.y, off);
        a0.z += __shfl_xor_sync(F, a0.z, off);
        a0.w += __shfl_xor_sync(F, a0.w, off);
        a1.x += __shfl_xor_sync(F, a1.x, off);
        a1.y += __shfl_xor_sync(F, a1.y, off);
        a1.z += __shfl_xor_sync(F, a1.z, off);
        a1.w += __shfl_xor_sync(F, a1.w, off);
    }
    // redistribute so lanes 0..15 write float4 index == lane (coalesced 256B)
    int tl = lane >> 1;
    float4 s0, s1;
    s0.x = __shfl_sync(F, a0.x, tl); s0.y = __shfl_sync(F, a0.y, tl);
    s0.z = __shfl_sync(F, a0.z, tl); s0.w = __shfl_sync(F, a0.w, tl);
    s1.x = __shfl_sync(F, a1.x, tl); s1.y = __shfl_sync(F, a1.y, tl);
    s1.z = __shfl_sync(F, a1.z, tl); s1.w = __shfl_sync(F, a1.w, tl);
    if (lane < 16) {
        float4* out4 = reinterpret_cast<float4*>(accOut);
        out4[(size_t)n * 16 + lane] = (lane & 1) ? s1 : s0;
    }
}

// ---------------------------------------------------------------------------
// Pool: per-graph sum of relu(dinv*acc3 + b3) with 4-node run-length batching.
__global__ void k_pool(const float* __restrict__ acc3, const float* __restrict__ b3,
                       const int* __restrict__ batch, int N) {
    int t = blockIdx.x * blockDim.x + threadIdx.x;
    int c = t & 63;
    int n0 = (t >> 6) * 4;
    if (n0 >= N) return;
    float b = b3[c];
    float accum = 0.f;
    int cnt = 0;
    int gprev = -1;
    for (int j = 0; j < 4; j++) {
        int n = n0 + j;
        if (n >= N) break;
        int g = batch[n];
        if ((unsigned)g >= NGRAPH) continue;
        if (g != gprev) {
            if (gprev >= 0) {
                atomicAdd(&g_gsum[gprev * NHID + c], accum);
                if (c == 0) atomicAdd(&g_gcnt[gprev], cnt);
            }
            accum = 0.f; cnt = 0; gprev = g;
        }
        accum += fmaxf(fmaf(g_dinv[n], acc3[(size_t)n * NHID + c], b), 0.f);
        cnt++;
    }
    if (gprev >= 0) {
        atomicAdd(&g_gsum[gprev * NHID + c], accum);
        if (c == 0) atomicAdd(&g_gcnt[gprev], cnt);
    }
}

__global__ void k_head(const float* __restrict__ Wl, const float* __restrict__ bl,
                       float* __restrict__ out) {
    int g = threadIdx.x;
    if (g >= NGRAPH) return;
    float cnt = fmaxf((float)g_gcnt[g], 1.f);
    float inv = 1.f / cnt;
    float l[NCLASS];
#pragma unroll
    for (int c = 0; c < NCLASS; c++) l[c] = bl[c];
    for (int k = 0; k < NHID; k++) {
        float p = g_gsum[g * NHID + k] * inv;
#pragma unroll
        for (int c = 0; c < NCLASS; c++) l[c] = fmaf(p, Wl[k * NCLASS + c], l[c]);
    }
    float m = l[0];
#pragma unroll
    for (int c = 1; c < NCLASS; c++) m = fmaxf(m, l[c]);
    float s = 0.f;
#pragma unroll
    for (int c = 0; c < NCLASS; c++) { l[c] = __expf(l[c] - m); s += l[c]; }
    float is = 1.f / s;
#pragma unroll
    for (int c = 0; c < NCLASS; c++) out[g * NCLASS + c] = l[c] * is;
}

// ---------------------------------------------------------------------------
extern "C" void kernel_launch(void* const* d_in, const int* in_sizes, int n_in,
                              void* d_out, int out_size) {
    const float* x     = (const float*)d_in[0];
    const int*   ei    = (const int*)d_in[1];
    const int*   batch = (const int*)d_in[2];
    const float* W1 = (const float*)d_in[3];
    const float* b1 = (const float*)d_in[4];
    const float* W2 = (const float*)d_in[5];
    const float* b2 = (const float*)d_in[6];
    const float* W3 = (const float*)d_in[7];
    const float* b3 = (const float*)d_in[8];
    const float* Wl = (const float*)d_in[9];
    const float* bl = (const float*)d_in[10];
    float* out = (float*)d_out;

    int N = in_sizes[0] / NFEAT;
    int E = in_sizes[1] / 2;

    float *accA = nullptr, *accB = nullptr;
    cudaGetSymbolAddress((void**)&accA, g_accA);
    cudaGetSymbolAddress((void**)&accB, g_accB);

    const int T = 256;
    int nScanBlocks = (N + SCAN_B - 1) / SCAN_B;

    k_init<<<(N + T - 1) / T, T>>>(N);
    k_edge_prep<<<(E + T - 1) / T, T>>>(ei, E, N);
    k_scanA<<<nScanBlocks, SCAN_B>>>(N);
    k_scanB<<<1, 256>>>(nScanBlocks);
    k_scanC<<<nScanBlocks, SCAN_B>>>(N);
    k_csr_fill<<<(E + T - 1) / T, T>>>(E);

    int gemmBlocks = (N + 31) / 32;
    int aggBlocks = (N * 32 + T - 1) / T;

    // Layer 1
    k_gemm1<<<gemmBlocks, 128>>>(x, W1, N);
    k_agg<<<aggBlocks, T>>>(accA, N);
    // Layer 2
    k_gemm23<<<gemmBlocks, 128>>>(accA, b1, W2, N);
    k_agg<<<aggBlocks, T>>>(accB, N);
    // Layer 3
    k_gemm23<<<gemmBlocks, 128>>>(accB, b2, W3, N);
    k_agg<<<aggBlocks, T>>>(accA, N);

    // Pool + head
    k_pool<<<(((N + 3) / 4) * 64 + T - 1) / T, T>>>(accA, b3, batch, N);
    k_head<<<1, 64>>>(Wl, bl, out);
}